// round 1
// baseline (speedup 1.0000x reference)
#include <cuda_runtime.h>
#include <cuda_bf16.h>
#include <float.h>

#define DIM   300
#define DIM4  75          // DIM / 4 float4 per row
#define MAXK  16

// Scratch (allocation-free rule: __device__ globals)
__device__ float g_wordvec[DIM];
__device__ float g_scores[200000];

// ---------------------------------------------------------------------------
// Kernel 0: fetch the query word's embedding row into a device global.
// ---------------------------------------------------------------------------
__global__ void fetch_wordvec_kernel(const int* __restrict__ wordid,
                                     const float* __restrict__ emb)
{
    int i = threadIdx.x;
    if (i < DIM) {
        long long w = (long long)wordid[0];
        g_wordvec[i] = emb[(size_t)w * DIM + i];
    }
}

// ---------------------------------------------------------------------------
// Kernel 1: scores[row] = dot(emb[row], wordvec).  Warp per row, float4 loads.
// 256 threads = 8 warps = 8 rows per block.  Fully coalesced streaming reads.
// ---------------------------------------------------------------------------
__global__ void scores_kernel(const float* __restrict__ emb, int V)
{
    __shared__ float4 swv[DIM4];
    int t = threadIdx.x;
    if (t < DIM4) swv[t] = reinterpret_cast<const float4*>(g_wordvec)[t];
    __syncthreads();

    int lane = t & 31;
    int warp = t >> 5;
    int row  = blockIdx.x * (blockDim.x >> 5) + warp;
    if (row >= V) return;

    const float4* rp = reinterpret_cast<const float4*>(emb + (size_t)row * DIM);

    float acc = 0.0f;
#pragma unroll
    for (int j = 0; j < 3; j++) {
        int idx = lane + 32 * j;
        if (idx < DIM4) {
            float4 a = rp[idx];
            float4 b = swv[idx];
            acc += a.x * b.x + a.y * b.y + a.z * b.z + a.w * b.w;
        }
    }
#pragma unroll
    for (int off = 16; off; off >>= 1)
        acc += __shfl_xor_sync(0xffffffffu, acc, off);

    if (lane == 0) g_scores[row] = acc;
}

// ---------------------------------------------------------------------------
// Kernel 2: single-block top-K over V scores.
//   per-thread insertion top-K  ->  per-warp butterfly argmax merge
//   ->  warp-0 final merge over 32*K candidates  ->  write out.
// Tie-break: larger value first; equal value -> smaller index (lax.top_k).
// out layout: out[0..K) = values, out[K..2K) = indices (as float).
// ---------------------------------------------------------------------------
__global__ void __launch_bounds__(1024, 1)
topk_kernel(float* __restrict__ out, int V, int K)
{
    const int T    = blockDim.x;          // 1024
    int tid  = threadIdx.x;
    int lane = tid & 31;
    int warp = tid >> 5;

    __shared__ float sv[32 * MAXK];
    __shared__ int   si[32 * MAXK];

    // --- per-thread top-K (sorted ascending: slot 0 = current min) ---
    float vals[MAXK];
    int   ids [MAXK];
    for (int j = 0; j < K; j++) { vals[j] = -FLT_MAX; ids[j] = 0x7fffffff; }

    for (int i = tid; i < V; i += T) {
        float s = g_scores[i];
        if (s > vals[0]) {
            int j = 0;
            while (j < K - 1 && s > vals[j + 1]) {
                vals[j] = vals[j + 1];
                ids [j] = ids [j + 1];
                j++;
            }
            vals[j] = s;
            ids [j] = i;
        }
    }

    // --- warp merge: K rounds of butterfly argmax (value desc, id asc) ---
    {
        int ptr = K - 1;
        for (int r = 0; r < K; r++) {
            float v  = (ptr >= 0) ? vals[ptr] : -FLT_MAX;
            int   id = (ptr >= 0) ? ids [ptr] : 0x7fffffff;
            float bv = v; int bid = id; int bl = lane;
#pragma unroll
            for (int off = 16; off; off >>= 1) {
                float ov  = __shfl_xor_sync(0xffffffffu, bv,  off);
                int   oid = __shfl_xor_sync(0xffffffffu, bid, off);
                int   ol  = __shfl_xor_sync(0xffffffffu, bl,  off);
                if (ov > bv || (ov == bv && oid < bid)) { bv = ov; bid = oid; bl = ol; }
            }
            if (lane == bl) ptr--;
            if (lane == 0) { sv[warp * K + r] = bv; si[warp * K + r] = bid; }
        }
    }
    __syncthreads();

    // --- final merge by warp 0 over 32*K candidates ---
    if (warp == 0) {
        float v2[MAXK];
        int   i2[MAXK];
        for (int j = 0; j < K; j++) { v2[j] = -FLT_MAX; i2[j] = 0x7fffffff; }

        for (int e = lane; e < 32 * K; e += 32) {
            float s  = sv[e];
            int   id = si[e];
            if (s > v2[0] || (s == v2[0] && id < i2[0])) {
                int j = 0;
                while (j < K - 1 &&
                       (s > v2[j + 1] || (s == v2[j + 1] && id < i2[j + 1]))) {
                    v2[j] = v2[j + 1];
                    i2[j] = i2[j + 1];
                    j++;
                }
                v2[j] = s;
                i2[j] = id;
            }
        }

        int ptr = K - 1;
        for (int r = 0; r < K; r++) {
            float v  = (ptr >= 0) ? v2[ptr] : -FLT_MAX;
            int   id = (ptr >= 0) ? i2[ptr] : 0x7fffffff;
            float bv = v; int bid = id; int bl = lane;
#pragma unroll
            for (int off = 16; off; off >>= 1) {
                float ov  = __shfl_xor_sync(0xffffffffu, bv,  off);
                int   oid = __shfl_xor_sync(0xffffffffu, bid, off);
                int   ol  = __shfl_xor_sync(0xffffffffu, bl,  off);
                if (ov > bv || (ov == bv && oid < bid)) { bv = ov; bid = oid; bl = ol; }
            }
            if (lane == bl) ptr--;
            if (lane == 0) {
                out[r]     = bv;
                out[K + r] = (float)bid;
            }
        }
    }
}

// ---------------------------------------------------------------------------
// kernel_launch
// Inputs (metadata order): wordid int32 [1], embedding float32 [V*300],
//                          topk int32 [1] (value fixed by out_size).
// Output: float32 [2K]: K values then K indices.
// ---------------------------------------------------------------------------
extern "C" void kernel_launch(void* const* d_in, const int* in_sizes, int n_in,
                              void* d_out, int out_size)
{
    const int*   wordid = (const int*)d_in[0];
    const float* emb    = (const float*)d_in[1];

    int V = in_sizes[1] / DIM;          // 200000
    int K = out_size / 2;               // topk + 1 = 11
    if (K > MAXK) K = MAXK;             // arrays bound (never hit for this problem)

    fetch_wordvec_kernel<<<1, 512>>>(wordid, emb);

    int rows_per_block = 256 / 32;      // 8 warps -> 8 rows
    int nblocks = (V + rows_per_block - 1) / rows_per_block;
    scores_kernel<<<nblocks, 256>>>(emb, V);

    topk_kernel<<<1, 1024>>>((float*)d_out, V, K);
}

// round 2
// speedup vs baseline: 2.9591x; 2.9591x over previous
#include <cuda_runtime.h>
#include <cuda_bf16.h>
#include <float.h>

#define DIM      300
#define DIM4     75           // DIM / 4 float4 per row
#define MAXK     16
#define TPB      256          // 8 warps per block
#define WPB      (TPB / 32)
#define NBLOCKS  1184         // 8 blocks per SM on 148 SMs

// Scratch (allocation-free rule: __device__ globals)
__device__ float        g_cand_v[NBLOCKS * MAXK];
__device__ int          g_cand_i[NBLOCKS * MAXK];
__device__ unsigned int g_done = 0;

// insertion into ascending-sorted top-K (slot 0 = current min)
__device__ __forceinline__ void topk_insert(float* vals, int* ids, int K,
                                            float s, int id)
{
    if (s > vals[0] || (s == vals[0] && id < ids[0])) {
        int j = 0;
        while (j < K - 1 &&
               (s > vals[j + 1] || (s == vals[j + 1] && id < ids[j + 1]))) {
            vals[j] = vals[j + 1];
            ids [j] = ids [j + 1];
            j++;
        }
        vals[j] = s;
        ids [j] = id;
    }
}

// K-round butterfly extraction of the warp-wide top-K from each lane's sorted
// candidate list (descending emit). emit(r, bv, bid) called on lane 0.
#define WARP_EXTRACT_TOPK(vals, ids, K, EMIT)                                  \
    do {                                                                       \
        int ptr = (K) - 1;                                                     \
        for (int r = 0; r < (K); r++) {                                        \
            float v  = (ptr >= 0) ? (vals)[ptr] : -FLT_MAX;                    \
            int   id = (ptr >= 0) ? (ids)[ptr]  : 0x7fffffff;                  \
            float bv = v; int bid = id; int bl = lane;                         \
            _Pragma("unroll")                                                  \
            for (int off = 16; off; off >>= 1) {                               \
                float ov  = __shfl_xor_sync(0xffffffffu, bv,  off);            \
                int   oid = __shfl_xor_sync(0xffffffffu, bid, off);            \
                int   ol  = __shfl_xor_sync(0xffffffffu, bl,  off);            \
                if (ov > bv || (ov == bv && oid < bid)) {                      \
                    bv = ov; bid = oid; bl = ol;                               \
                }                                                              \
            }                                                                  \
            if (lane == bl) ptr--;                                             \
            if (lane == 0) { EMIT; }                                           \
        }                                                                      \
    } while (0)

__device__ __forceinline__ float dot_row(const float4* __restrict__ rp,
                                         int lane,
                                         float4 b0, float4 b1, float4 b2)
{
    float4 a0 = rp[lane];
    float4 a1 = rp[lane + 32];
    float acc = a0.x * b0.x + a0.y * b0.y + a0.z * b0.z + a0.w * b0.w
              + a1.x * b1.x + a1.y * b1.y + a1.z * b1.z + a1.w * b1.w;
    if (lane < DIM4 - 64) {                     // lanes 0..10 cover idx 64..74
        float4 a2 = rp[lane + 64];
        acc += a2.x * b2.x + a2.y * b2.y + a2.z * b2.z + a2.w * b2.w;
    }
    return acc;
}

__device__ __forceinline__ float warp_sum(float acc)
{
#pragma unroll
    for (int off = 16; off; off >>= 1)
        acc += __shfl_xor_sync(0xffffffffu, acc, off);
    return acc;
}

// ---------------------------------------------------------------------------
// Fused kernel: scores + hierarchical top-K + last-block final merge.
// ---------------------------------------------------------------------------
__global__ void __launch_bounds__(TPB, 8)
fused_sim_topk_kernel(const int* __restrict__ wordid,
                      const float* __restrict__ emb,
                      float* __restrict__ out,
                      int V, int K)
{
    __shared__ float4 swv[DIM4];
    __shared__ float  sv[WPB * MAXK];
    __shared__ int    si[WPB * MAXK];
    __shared__ int    s_last;

    const int tid  = threadIdx.x;
    const int lane = tid & 31;
    const int warp = tid >> 5;

    // --- broadcast the query word vector into shared, then registers ---
    if (tid < DIM4) {
        long long w = (long long)wordid[0];
        swv[tid] = reinterpret_cast<const float4*>(emb + (size_t)w * DIM)[tid];
    }
    __syncthreads();

    const float4 b0 = swv[lane];
    const float4 b1 = swv[lane + 32];
    const float4 b2 = (lane < DIM4 - 64) ? swv[lane + 64]
                                         : make_float4(0.f, 0.f, 0.f, 0.f);

    // --- phase 1: streaming dot products, per-warp top-K in lane 0 ---
    float vals[MAXK];
    int   ids [MAXK];
#pragma unroll
    for (int j = 0; j < MAXK; j++) { vals[j] = -FLT_MAX; ids[j] = 0x7fffffff; }

    const int total_warps = gridDim.x * WPB;
    const int gw = blockIdx.x * WPB + warp;

    int row = gw;
    // 2-row unroll for higher MLP
    for (; row + total_warps < V; row += 2 * total_warps) {
        const float4* rp0 = reinterpret_cast<const float4*>(emb + (size_t)row * DIM);
        const float4* rp1 = reinterpret_cast<const float4*>(emb + (size_t)(row + total_warps) * DIM);
        float acc0 = dot_row(rp0, lane, b0, b1, b2);
        float acc1 = dot_row(rp1, lane, b0, b1, b2);
        acc0 = warp_sum(acc0);
        acc1 = warp_sum(acc1);
        if (lane == 0) {
            topk_insert(vals, ids, K, acc0, row);
            topk_insert(vals, ids, K, acc1, row + total_warps);
        }
    }
    for (; row < V; row += total_warps) {
        const float4* rp = reinterpret_cast<const float4*>(emb + (size_t)row * DIM);
        float acc = warp_sum(dot_row(rp, lane, b0, b1, b2));
        if (lane == 0) topk_insert(vals, ids, K, acc, row);
    }

    // lane 0 holds this warp's top-K (ascending). Broadcast to all lanes so
    // the butterfly extraction works: instead, just have lane 0 dump to smem.
    if (lane == 0) {
#pragma unroll
        for (int j = 0; j < MAXK; j++) {
            if (j < K) { sv[warp * K + j] = vals[j]; si[warp * K + j] = ids[j]; }
        }
    }
    __syncthreads();

    // --- phase 2: warp 0 merges the block's WPB*K candidates -> g_cand ---
    if (warp == 0) {
        float v2[MAXK];
        int   i2[MAXK];
#pragma unroll
        for (int j = 0; j < MAXK; j++) { v2[j] = -FLT_MAX; i2[j] = 0x7fffffff; }
        for (int e = lane; e < WPB * K; e += 32)
            topk_insert(v2, i2, K, sv[e], si[e]);

        float* gv = g_cand_v + (size_t)blockIdx.x * K;
        int*   gi = g_cand_i + (size_t)blockIdx.x * K;
        WARP_EXTRACT_TOPK(v2, i2, K, { gv[r] = bv; gi[r] = bid; });
    }

    // --- phase 3: last block to finish does the final merge ---
    __threadfence();
    if (tid == 0) {
        unsigned int prev = atomicAdd(&g_done, 1u);
        s_last = (prev == gridDim.x - 1) ? 1 : 0;
    }
    __syncthreads();
    if (!s_last) return;

    {
        const int NC = gridDim.x * K;
        float v3[MAXK];
        int   i3[MAXK];
#pragma unroll
        for (int j = 0; j < MAXK; j++) { v3[j] = -FLT_MAX; i3[j] = 0x7fffffff; }
        for (int e = tid; e < NC; e += TPB)
            topk_insert(v3, i3, K, g_cand_v[e], g_cand_i[e]);

        // per-warp butterfly -> smem
        WARP_EXTRACT_TOPK(v3, i3, K, { sv[warp * K + r] = bv; si[warp * K + r] = bid; });
        __syncthreads();

        if (warp == 0) {
            float v4[MAXK];
            int   i4[MAXK];
#pragma unroll
            for (int j = 0; j < MAXK; j++) { v4[j] = -FLT_MAX; i4[j] = 0x7fffffff; }
            for (int e = lane; e < WPB * K; e += 32)
                topk_insert(v4, i4, K, sv[e], si[e]);

            WARP_EXTRACT_TOPK(v4, i4, K, {
                out[r]     = bv;
                out[K + r] = (float)bid;
            });
        }

        // reset counter for the next (deterministic) replay
        __syncthreads();
        if (tid == 0) g_done = 0;
    }
}

// ---------------------------------------------------------------------------
// kernel_launch — single fused kernel.
// Inputs: wordid int32 [1], embedding float32 [V*300], topk int32 [1].
// Output: float32 [2K]: K values then K indices (K = topk+1 = out_size/2).
// ---------------------------------------------------------------------------
extern "C" void kernel_launch(void* const* d_in, const int* in_sizes, int n_in,
                              void* d_out, int out_size)
{
    const int*   wordid = (const int*)d_in[0];
    const float* emb    = (const float*)d_in[1];

    int V = in_sizes[1] / DIM;       // 200000
    int K = out_size / 2;            // 11
    if (K > MAXK) K = MAXK;

    fused_sim_topk_kernel<<<NBLOCKS, TPB>>>(wordid, emb, (float*)d_out, V, K);
}

// round 3
// speedup vs baseline: 3.6971x; 1.2494x over previous
#include <cuda_runtime.h>
#include <cuda_bf16.h>
#include <float.h>

#define DIM            300
#define DIM4           75                       // float4 per row
#define MAXK           16
#define TPB            512                      // 16 warps
#define WPB            (TPB / 32)
#define NB             148                      // 1 persistent block per SM
#define ROWS_PER_STAGE 32
#define STAGE_F4       (ROWS_PER_STAGE * DIM4)  // 2400 float4 = 38400 B
#define NSTAGES        5
#define SMEM_BYTES     (NSTAGES * STAGE_F4 * 16)  // 192000 B

// Scratch (allocation-free rule: __device__ globals)
__device__ float        g_cand_v[NB * MAXK];
__device__ int          g_cand_i[NB * MAXK];
__device__ unsigned int g_done = 0;

// ---------------------------------------------------------------------------
// helpers
// ---------------------------------------------------------------------------
__device__ __forceinline__ void cp16(unsigned int saddr, const void* gaddr)
{
    asm volatile("cp.async.cg.shared.global [%0], [%1], 16;\n"
                 :: "r"(saddr), "l"(gaddr));
}

// insertion into ascending-sorted top-K (slot 0 = current min)
__device__ __forceinline__ void topk_insert(float* vals, int* ids, int K,
                                            float s, int id)
{
    if (s > vals[0] || (s == vals[0] && id < ids[0])) {
        int j = 0;
        while (j < K - 1 &&
               (s > vals[j + 1] || (s == vals[j + 1] && id < ids[j + 1]))) {
            vals[j] = vals[j + 1];
            ids [j] = ids [j + 1];
            j++;
        }
        vals[j] = s;
        ids [j] = id;
    }
}

// K-round butterfly extraction of the warp-wide top-K (descending emit).
#define WARP_EXTRACT_TOPK(vals, ids, K, EMIT)                                  \
    do {                                                                       \
        int ptr = (K) - 1;                                                     \
        for (int r = 0; r < (K); r++) {                                        \
            float v  = (ptr >= 0) ? (vals)[ptr] : -FLT_MAX;                    \
            int   id = (ptr >= 0) ? (ids)[ptr]  : 0x7fffffff;                  \
            float bv = v; int bid = id; int bl = lane;                         \
            _Pragma("unroll")                                                  \
            for (int off = 16; off; off >>= 1) {                               \
                float ov  = __shfl_xor_sync(0xffffffffu, bv,  off);            \
                int   oid = __shfl_xor_sync(0xffffffffu, bid, off);            \
                int   ol  = __shfl_xor_sync(0xffffffffu, bl,  off);            \
                if (ov > bv || (ov == bv && oid < bid)) {                      \
                    bv = ov; bid = oid; bl = ol;                               \
                }                                                              \
            }                                                                  \
            if (lane == bl) ptr--;                                             \
            if (lane == 0) { EMIT; }                                           \
        }                                                                      \
    } while (0)

__device__ __forceinline__ float dot_row(const float4* __restrict__ rp,
                                         int lane,
                                         float4 b0, float4 b1, float4 b2)
{
    float4 a0 = rp[lane];
    float4 a1 = rp[lane + 32];
    float acc = a0.x * b0.x + a0.y * b0.y + a0.z * b0.z + a0.w * b0.w
              + a1.x * b1.x + a1.y * b1.y + a1.z * b1.z + a1.w * b1.w;
    if (lane < DIM4 - 64) {                     // lanes 0..10 cover idx 64..74
        float4 a2 = rp[lane + 64];
        acc += a2.x * b2.x + a2.y * b2.y + a2.z * b2.z + a2.w * b2.w;
    }
    return acc;
}

__device__ __forceinline__ float warp_sum(float acc)
{
#pragma unroll
    for (int off = 16; off; off >>= 1)
        acc += __shfl_xor_sync(0xffffffffu, acc, off);
    return acc;
}

// ---------------------------------------------------------------------------
// Fused persistent kernel: cp.async staged GEMV + hierarchical top-K.
// ---------------------------------------------------------------------------
__global__ void __launch_bounds__(TPB, 1)
fused_sim_topk_kernel(const int* __restrict__ wordid,
                      const float* __restrict__ emb,
                      float* __restrict__ out,
                      int V, int K)
{
    extern __shared__ float4 sbuf[];            // NSTAGES * STAGE_F4 float4
    __shared__ float4 swv[DIM4];
    __shared__ float  sv[WPB * MAXK];
    __shared__ int    si[WPB * MAXK];
    __shared__ int    s_last;

    const int tid  = threadIdx.x;
    const int lane = tid & 31;
    const int warp = tid >> 5;

    // --- query word vector -> shared -> registers ---
    {
        int w = wordid[0];
        if (tid < DIM4)
            swv[tid] = reinterpret_cast<const float4*>(emb + (size_t)w * DIM)[tid];
    }
    __syncthreads();
    const float4 b0 = swv[lane];
    const float4 b1 = swv[lane + 32];
    const float4 b2 = (lane < DIM4 - 64) ? swv[lane + 64]
                                         : make_float4(0.f, 0.f, 0.f, 0.f);

    // --- this block's contiguous row chunk ---
    const int chunk    = (V + NB - 1) / NB;
    const int row_base = blockIdx.x * chunk;
    int rows_blk = V - row_base;
    if (rows_blk > chunk) rows_blk = chunk;
    if (rows_blk < 0)     rows_blk = 0;
    const int ntiles = (rows_blk + ROWS_PER_STAGE - 1) / ROWS_PER_STAGE;

    const float4* gbase = reinterpret_cast<const float4*>(emb + (size_t)row_base * DIM);
    const unsigned int sbase =
        (unsigned int)__cvta_generic_to_shared(sbuf);

    // --- prologue: fill the pipeline (always commit NSTAGES groups) ---
    for (int s = 0; s < NSTAGES; s++) {
        if (s < ntiles) {
            int rows_v = rows_blk - s * ROWS_PER_STAGE;
            if (rows_v > ROWS_PER_STAGE) rows_v = ROWS_PER_STAGE;
            const int n4 = rows_v * DIM4;
            const float4* src = gbase + (size_t)s * STAGE_F4;
            const unsigned int dst = sbase + (s % NSTAGES) * STAGE_F4 * 16;
            for (int i = tid; i < n4; i += TPB)
                cp16(dst + i * 16, src + i);
        }
        asm volatile("cp.async.commit_group;");
    }

    // --- per-warp running top-K (lane 0 holds it) ---
    float vals[MAXK];
    int   ids [MAXK];
#pragma unroll
    for (int j = 0; j < MAXK; j++) { vals[j] = -FLT_MAX; ids[j] = 0x7fffffff; }

    // --- main pipeline loop ---
    for (int s = 0; s < ntiles; s++) {
        asm volatile("cp.async.wait_group %0;" :: "n"(NSTAGES - 1));
        __syncthreads();

        int rows_v = rows_blk - s * ROWS_PER_STAGE;
        if (rows_v > ROWS_PER_STAGE) rows_v = ROWS_PER_STAGE;
        const float4* buf = sbuf + (s % NSTAGES) * STAGE_F4;

        for (int r = warp; r < rows_v; r += WPB) {
            float acc = warp_sum(dot_row(buf + r * DIM4, lane, b0, b1, b2));
            if (lane == 0)
                topk_insert(vals, ids, K, acc,
                            row_base + s * ROWS_PER_STAGE + r);
        }
        __syncthreads();

        const int ns = s + NSTAGES;
        if (ns < ntiles) {
            int rows_n = rows_blk - ns * ROWS_PER_STAGE;
            if (rows_n > ROWS_PER_STAGE) rows_n = ROWS_PER_STAGE;
            const int n4 = rows_n * DIM4;
            const float4* src = gbase + (size_t)ns * STAGE_F4;
            const unsigned int dst = sbase + (ns % NSTAGES) * STAGE_F4 * 16;
            for (int i = tid; i < n4; i += TPB)
                cp16(dst + i * 16, src + i);
        }
        asm volatile("cp.async.commit_group;");
    }
    asm volatile("cp.async.wait_group 0;");

    // --- phase 2: block merge -> per-block candidates in gmem ---
    if (lane == 0) {
#pragma unroll
        for (int j = 0; j < MAXK; j++) {
            if (j < K) { sv[warp * K + j] = vals[j]; si[warp * K + j] = ids[j]; }
        }
    }
    __syncthreads();

    if (warp == 0) {
        float v2[MAXK];
        int   i2[MAXK];
#pragma unroll
        for (int j = 0; j < MAXK; j++) { v2[j] = -FLT_MAX; i2[j] = 0x7fffffff; }
        for (int e = lane; e < WPB * K; e += 32)
            topk_insert(v2, i2, K, sv[e], si[e]);

        float* gv = g_cand_v + (size_t)blockIdx.x * K;
        int*   gi = g_cand_i + (size_t)blockIdx.x * K;
        WARP_EXTRACT_TOPK(v2, i2, K, { gv[r] = bv; gi[r] = bid; });
    }

    // --- phase 3: last block to finish does the final merge ---
    __threadfence();
    if (tid == 0) {
        unsigned int prev = atomicAdd(&g_done, 1u);
        s_last = (prev == gridDim.x - 1) ? 1 : 0;
    }
    __syncthreads();
    if (!s_last) return;

    {
        const int NC = gridDim.x * K;
        float v3[MAXK];
        int   i3[MAXK];
#pragma unroll
        for (int j = 0; j < MAXK; j++) { v3[j] = -FLT_MAX; i3[j] = 0x7fffffff; }
        for (int e = tid; e < NC; e += TPB)
            topk_insert(v3, i3, K, g_cand_v[e], g_cand_i[e]);

        WARP_EXTRACT_TOPK(v3, i3, K, { sv[warp * K + r] = bv; si[warp * K + r] = bid; });
        __syncthreads();

        if (warp == 0) {
            float v4[MAXK];
            int   i4[MAXK];
#pragma unroll
            for (int j = 0; j < MAXK; j++) { v4[j] = -FLT_MAX; i4[j] = 0x7fffffff; }
            for (int e = lane; e < WPB * K; e += 32)
                topk_insert(v4, i4, K, sv[e], si[e]);

            WARP_EXTRACT_TOPK(v4, i4, K, {
                out[r]     = bv;
                out[K + r] = (float)bid;
            });
        }

        __syncthreads();
        if (tid == 0) g_done = 0;   // reset for deterministic graph replay
    }
}

// ---------------------------------------------------------------------------
// kernel_launch — single fused persistent kernel.
// Inputs: wordid int32 [1], embedding float32 [V*300], topk int32 [1].
// Output: float32 [2K]: K values then K indices (K = topk+1 = out_size/2).
// ---------------------------------------------------------------------------
extern "C" void kernel_launch(void* const* d_in, const int* in_sizes, int n_in,
                              void* d_out, int out_size)
{
    const int*   wordid = (const int*)d_in[0];
    const float* emb    = (const float*)d_in[1];

    int V = in_sizes[1] / DIM;       // 200000
    int K = out_size / 2;            // 11
    if (K > MAXK) K = MAXK;

    cudaFuncSetAttribute(fused_sim_topk_kernel,
                         cudaFuncAttributeMaxDynamicSharedMemorySize,
                         SMEM_BYTES);

    fused_sim_topk_kernel<<<NB, TPB, SMEM_BYTES>>>(wordid, emb,
                                                   (float*)d_out, V, K);
}

// round 4
// speedup vs baseline: 4.0192x; 1.0871x over previous
#include <cuda_runtime.h>
#include <cuda_bf16.h>
#include <float.h>
#include <stdint.h>

#define DIM            300
#define DIM4           75                        // float4 per row
#define MAXK           16
#define TPB            512                       // 16 warps
#define WPB            (TPB / 32)
#define NB             148                       // 1 persistent block per SM
#define ROWS_PER_STAGE 32
#define STAGE_BYTES    (ROWS_PER_STAGE * DIM * 4)   // 38400
#define STAGE_F4       (ROWS_PER_STAGE * DIM4)      // 2400 float4
#define NSTAGES        5
#define SMEM_BYTES     (NSTAGES * STAGE_BYTES)      // 192000

// Scratch (allocation-free rule: __device__ globals)
__device__ float        g_cand_v[NB * MAXK];
__device__ int          g_cand_i[NB * MAXK];
__device__ unsigned int g_done = 0;

// ---------------------------------------------------------------------------
// PTX helpers
// ---------------------------------------------------------------------------
__device__ __forceinline__ unsigned smem_u32(const void* p)
{
    return (unsigned)__cvta_generic_to_shared(p);
}

__device__ __forceinline__ void mbar_init(unsigned mbar, unsigned count)
{
    asm volatile("mbarrier.init.shared.b64 [%0], %1;" :: "r"(mbar), "r"(count) : "memory");
}

__device__ __forceinline__ void mbar_expect_tx(unsigned mbar, unsigned bytes)
{
    asm volatile("mbarrier.arrive.expect_tx.shared.b64 _, [%0], %1;"
                 :: "r"(mbar), "r"(bytes) : "memory");
}

__device__ __forceinline__ void mbar_wait(unsigned mbar, unsigned phase)
{
    unsigned done;
    asm volatile("{\n\t.reg .pred p;\n\t"
                 "mbarrier.try_wait.parity.shared.b64 p, [%1], %2;\n\t"
                 "selp.b32 %0, 1, 0, p;\n\t}"
                 : "=r"(done) : "r"(mbar), "r"(phase) : "memory");
    if (!done) {
        asm volatile("{\n\t.reg .pred P1;\n\t"
                     "W_%=:\n\t"
                     "mbarrier.try_wait.parity.shared.b64 P1, [%0], %1, 0x989680;\n\t"
                     "@P1 bra.uni D_%=;\n\t"
                     "bra.uni W_%=;\n\t"
                     "D_%=:\n\t}"
                     :: "r"(mbar), "r"(phase) : "memory");
    }
}

// 1D bulk copy gmem -> smem through the TMA path, completion via mbarrier tx.
__device__ __forceinline__ void bulk_g2s(unsigned dst, const void* src,
                                         unsigned bytes, unsigned mbar)
{
    asm volatile("cp.async.bulk.shared::cta.global.mbarrier::complete_tx::bytes "
                 "[%0], [%1], %2, [%3];"
                 :: "r"(dst), "l"(src), "r"(bytes), "r"(mbar) : "memory");
}

__device__ __forceinline__ void fence_async_smem()
{
    asm volatile("fence.proxy.async.shared::cta;" ::: "memory");
}

// ---------------------------------------------------------------------------
// top-K helpers (ascending-sorted register list; slot 0 = current min)
// ---------------------------------------------------------------------------
__device__ __forceinline__ void topk_insert(float* vals, int* ids, int K,
                                            float s, int id)
{
    if (s > vals[0] || (s == vals[0] && id < ids[0])) {
        int j = 0;
        while (j < K - 1 &&
               (s > vals[j + 1] || (s == vals[j + 1] && id < ids[j + 1]))) {
            vals[j] = vals[j + 1];
            ids [j] = ids [j + 1];
            j++;
        }
        vals[j] = s;
        ids [j] = id;
    }
}

#define WARP_EXTRACT_TOPK(vals, ids, K, EMIT)                                  \
    do {                                                                       \
        int ptr = (K) - 1;                                                     \
        for (int r = 0; r < (K); r++) {                                        \
            float v  = (ptr >= 0) ? (vals)[ptr] : -FLT_MAX;                    \
            int   id = (ptr >= 0) ? (ids)[ptr]  : 0x7fffffff;                  \
            float bv = v; int bid = id; int bl = lane;                         \
            _Pragma("unroll")                                                  \
            for (int off = 16; off; off >>= 1) {                               \
                float ov  = __shfl_xor_sync(0xffffffffu, bv,  off);            \
                int   oid = __shfl_xor_sync(0xffffffffu, bid, off);            \
                int   ol  = __shfl_xor_sync(0xffffffffu, bl,  off);            \
                if (ov > bv || (ov == bv && oid < bid)) {                      \
                    bv = ov; bid = oid; bl = ol;                               \
                }                                                              \
            }                                                                  \
            if (lane == bl) ptr--;                                             \
            if (lane == 0) { EMIT; }                                           \
        }                                                                      \
    } while (0)

__device__ __forceinline__ float dot_row(const float4* __restrict__ rp,
                                         int lane,
                                         float4 b0, float4 b1, float4 b2)
{
    float4 a0 = rp[lane];
    float4 a1 = rp[lane + 32];
    float acc = a0.x * b0.x + a0.y * b0.y + a0.z * b0.z + a0.w * b0.w
              + a1.x * b1.x + a1.y * b1.y + a1.z * b1.z + a1.w * b1.w;
    if (lane < DIM4 - 64) {
        float4 a2 = rp[lane + 64];
        acc += a2.x * b2.x + a2.y * b2.y + a2.z * b2.z + a2.w * b2.w;
    }
    return acc;
}

__device__ __forceinline__ float warp_sum(float acc)
{
#pragma unroll
    for (int off = 16; off; off >>= 1)
        acc += __shfl_xor_sync(0xffffffffu, acc, off);
    return acc;
}

// ---------------------------------------------------------------------------
// Fused persistent kernel: TMA-bulk staged GEMV + hierarchical top-K.
// ---------------------------------------------------------------------------
__global__ void __launch_bounds__(TPB, 1)
fused_sim_topk_kernel(const int* __restrict__ wordid,
                      const float* __restrict__ emb,
                      float* __restrict__ out,
                      int V, int K)
{
    extern __shared__ float4 sbuf[];             // NSTAGES stage buffers
    __shared__ float4   swv[DIM4];
    __shared__ float    sv[WPB * MAXK];
    __shared__ int      si[WPB * MAXK];
    __shared__ int      s_last;
    __shared__ __align__(8) unsigned long long mbar_full[NSTAGES];

    const int tid  = threadIdx.x;
    const int lane = tid & 31;
    const int warp = tid >> 5;

    // --- init mbarriers + fetch query word vector ---
    if (tid == 0) {
#pragma unroll
        for (int s = 0; s < NSTAGES; s++)
            mbar_init(smem_u32(&mbar_full[s]), 1);
        fence_async_smem();
    }
    {
        int w = wordid[0];
        if (tid < DIM4)
            swv[tid] = reinterpret_cast<const float4*>(emb + (size_t)w * DIM)[tid];
    }
    __syncthreads();

    const float4 b0 = swv[lane];
    const float4 b1 = swv[lane + 32];
    const float4 b2 = (lane < DIM4 - 64) ? swv[lane + 64]
                                         : make_float4(0.f, 0.f, 0.f, 0.f);

    // --- this block's contiguous row chunk ---
    const int chunk    = (V + NB - 1) / NB;
    const int row_base = blockIdx.x * chunk;
    int rows_blk = V - row_base;
    if (rows_blk > chunk) rows_blk = chunk;
    if (rows_blk < 0)     rows_blk = 0;
    const int ntiles = (rows_blk + ROWS_PER_STAGE - 1) / ROWS_PER_STAGE;

    const char* gbase = reinterpret_cast<const char*>(emb + (size_t)row_base * DIM);
    const unsigned sbase = smem_u32(sbuf);

    // --- prologue: fill the pipeline ---
    if (tid == 0) {
        int np = (ntiles < NSTAGES) ? ntiles : NSTAGES;
        for (int s = 0; s < np; s++) {
            int rows_v = rows_blk - s * ROWS_PER_STAGE;
            if (rows_v > ROWS_PER_STAGE) rows_v = ROWS_PER_STAGE;
            unsigned bytes = (unsigned)rows_v * (DIM * 4);
            unsigned mb = smem_u32(&mbar_full[s]);
            mbar_expect_tx(mb, bytes);
            bulk_g2s(sbase + s * STAGE_BYTES,
                     gbase + (size_t)s * STAGE_BYTES, bytes, mb);
        }
    }

    // --- per-warp running top-K (lane 0 holds it) ---
    float vals[MAXK];
    int   ids [MAXK];
#pragma unroll
    for (int j = 0; j < MAXK; j++) { vals[j] = -FLT_MAX; ids[j] = 0x7fffffff; }

    // --- main pipeline loop ---
    int slot = 0, phase = 0;
    for (int s = 0; s < ntiles; s++) {
        mbar_wait(smem_u32(&mbar_full[slot]), phase);

        int rows_v = rows_blk - s * ROWS_PER_STAGE;
        if (rows_v > ROWS_PER_STAGE) rows_v = ROWS_PER_STAGE;
        const float4* buf = sbuf + slot * STAGE_F4;

        for (int r = warp; r < rows_v; r += WPB) {
            float acc = warp_sum(dot_row(buf + r * DIM4, lane, b0, b1, b2));
            if (lane == 0)
                topk_insert(vals, ids, K, acc,
                            row_base + s * ROWS_PER_STAGE + r);
        }
        __syncthreads();   // everyone done reading this slot

        const int ns = s + NSTAGES;
        if (tid == 0 && ns < ntiles) {
            int rows_n = rows_blk - ns * ROWS_PER_STAGE;
            if (rows_n > ROWS_PER_STAGE) rows_n = ROWS_PER_STAGE;
            unsigned bytes = (unsigned)rows_n * (DIM * 4);
            unsigned mb = smem_u32(&mbar_full[slot]);
            fence_async_smem();
            mbar_expect_tx(mb, bytes);
            bulk_g2s(sbase + slot * STAGE_BYTES,
                     gbase + (size_t)ns * STAGE_BYTES, bytes, mb);
        }

        if (++slot == NSTAGES) { slot = 0; phase ^= 1; }
    }

    // --- phase 2: block merge -> per-block candidates in gmem ---
    if (lane == 0) {
#pragma unroll
        for (int j = 0; j < MAXK; j++) {
            if (j < K) { sv[warp * K + j] = vals[j]; si[warp * K + j] = ids[j]; }
        }
    }
    __syncthreads();

    if (warp == 0) {
        float v2[MAXK];
        int   i2[MAXK];
#pragma unroll
        for (int j = 0; j < MAXK; j++) { v2[j] = -FLT_MAX; i2[j] = 0x7fffffff; }
        for (int e = lane; e < WPB * K; e += 32)
            topk_insert(v2, i2, K, sv[e], si[e]);

        float* gv = g_cand_v + (size_t)blockIdx.x * K;
        int*   gi = g_cand_i + (size_t)blockIdx.x * K;
        WARP_EXTRACT_TOPK(v2, i2, K, { gv[r] = bv; gi[r] = bid; });
    }

    // --- phase 3: last block to finish does the final merge ---
    __threadfence();
    if (tid == 0) {
        unsigned int prev = atomicAdd(&g_done, 1u);
        s_last = (prev == gridDim.x - 1) ? 1 : 0;
    }
    __syncthreads();
    if (!s_last) return;

    {
        const int NC = gridDim.x * K;
        float v3[MAXK];
        int   i3[MAXK];
#pragma unroll
        for (int j = 0; j < MAXK; j++) { v3[j] = -FLT_MAX; i3[j] = 0x7fffffff; }
        for (int e = tid; e < NC; e += TPB)
            topk_insert(v3, i3, K, g_cand_v[e], g_cand_i[e]);

        WARP_EXTRACT_TOPK(v3, i3, K, { sv[warp * K + r] = bv; si[warp * K + r] = bid; });
        __syncthreads();

        if (warp == 0) {
            float v4[MAXK];
            int   i4[MAXK];
#pragma unroll
            for (int j = 0; j < MAXK; j++) { v4[j] = -FLT_MAX; i4[j] = 0x7fffffff; }
            for (int e = lane; e < WPB * K; e += 32)
                topk_insert(v4, i4, K, sv[e], si[e]);

            WARP_EXTRACT_TOPK(v4, i4, K, {
                out[r]     = bv;
                out[K + r] = (float)bid;
            });
        }

        __syncthreads();
        if (tid == 0) g_done = 0;   // reset for deterministic graph replay
    }
}

// ---------------------------------------------------------------------------
// kernel_launch — single fused persistent kernel.
// Inputs: wordid int32 [1], embedding float32 [V*300], topk int32 [1].
// Output: float32 [2K]: K values then K indices (K = topk+1 = out_size/2).
// ---------------------------------------------------------------------------
extern "C" void kernel_launch(void* const* d_in, const int* in_sizes, int n_in,
                              void* d_out, int out_size)
{
    const int*   wordid = (const int*)d_in[0];
    const float* emb    = (const float*)d_in[1];

    int V = in_sizes[1] / DIM;       // 200000
    int K = out_size / 2;            // 11
    if (K > MAXK) K = MAXK;

    cudaFuncSetAttribute(fused_sim_topk_kernel,
                         cudaFuncAttributeMaxDynamicSharedMemorySize,
                         SMEM_BYTES);

    fused_sim_topk_kernel<<<NB, TPB, SMEM_BYTES>>>(wordid, emb,
                                                   (float*)d_out, V, K);
}